// round 1
// baseline (speedup 1.0000x reference)
#include <cuda_runtime.h>
#include <cstddef>

#define BATCH 32
#define DCH 256
#define NG 64
#define PTOT 1040

// cumulative position offsets per layer (31 layers)
__constant__ int c_off[31] = {0,63,125,186,246,305,363,420,476,531,585,638,690,741,791,
                              840,864,887,909,930,950,969,987,
                              1004,1012,1019,1025,1030,1034,1037,1039};

static const int h_off[31] = {0,63,125,186,246,305,363,420,476,531,585,638,690,741,791,
                              840,864,887,909,930,950,969,987,
                              1004,1012,1019,1025,1030,1034,1037,1039};

// ---------------- scratch (static device allocations) ----------------
__device__ float g_wT2[29 * 512 * 256];       // transposed ksz=2 weights [29][K=512][N=256]
__device__ float g_wT3[2 * 768 * 256];        // transposed ksz=3 weights [2][K=768][N=256]
__device__ float g_wTv[768 * 256];            // transposed vis_w        [768][256]
__device__ float g_cur[(size_t)BATCH * DCH * PTOT];   // all conv layer outputs [B][C][1040]
__device__ float g_Pc[(size_t)BATCH * PTOT * DCH];    // W2 @ cur  [B][1040][256]
__device__ float g_P1[BATCH * NG * DCH];              // W1 @ x    [B][64][256]
__device__ float g_P2x[BATCH * NG * DCH];             // W2 @ x
__device__ float g_P3[BATCH * NG * DCH];              // W3 @ x

// ---------------- batched transpose: in [bat][R][C] -> out [bat][C][R] ----------------
__global__ void transpose_batched(const float* __restrict__ in, float* __restrict__ out,
                                  int R, int C) {
    __shared__ float tile[32][33];
    int bat = blockIdx.z;
    int c0 = blockIdx.x * 32, r0 = blockIdx.y * 32;
    const float* ib = in + (size_t)bat * R * C;
    float* ob = out + (size_t)bat * R * C;
    int tx = threadIdx.x, ty = threadIdx.y;  // 32 x 8
#pragma unroll
    for (int s = 0; s < 32; s += 8) {
        int r = r0 + ty + s, c = c0 + tx;
        if (r < R && c < C) tile[ty + s][tx] = ib[(size_t)r * C + c];
    }
    __syncthreads();
#pragma unroll
    for (int s = 0; s < 32; s += 8) {
        int c = c0 + ty + s, r = r0 + tx;
        if (c < C && r < R) ob[(size_t)c * R + r] = tile[tx][ty + s];
    }
}

// ---------------- conv-as-GEMM ----------------
// out[b, n, m] = bias[n] + sum_{c,kk} in[b, c, m*cstride+kk] * wT[c*KSZ+kk][n]
// A tile [KC][64] from input rows, B tile [KC][64] from transposed weights.
// Block: 256 threads, 64(M) x 64(N) tile, 4x4 register tile per thread.
template <int KSZ, bool TRANS>
__global__ void __launch_bounds__(256) conv_gemm(
    const float* __restrict__ in, int in_row_len, int in_off, int cstride,
    const float* __restrict__ wT, const float* __restrict__ bias,
    float* __restrict__ out, int out_row_len, int out_off, int L_out) {
    constexpr int KC = (KSZ == 3) ? 24 : 16;
    constexpr int CPC = KC / KSZ;  // channels per chunk

    __shared__ float As[KC][64];
    __shared__ float Bs[KC][64];

    int b = blockIdx.z;
    int nblk = blockIdx.y * 64;
    int mblk = blockIdx.x * 64;

    int tid = threadIdx.x;
    int m0 = (tid / 16) * 4;
    int n0 = (tid % 16) * 4;

    float acc[4][4];
#pragma unroll
    for (int ni = 0; ni < 4; ni++) {
        float bv = bias ? __ldg(bias + nblk + n0 + ni) : 0.f;
#pragma unroll
        for (int mi = 0; mi < 4; mi++) acc[mi][ni] = bv;
    }

    const float* inb = in + (size_t)b * DCH * in_row_len + in_off;

    for (int c0 = 0; c0 < DCH; c0 += CPC) {
        // load A
#pragma unroll
        for (int e = tid; e < KC * 64; e += 256) {
            int k = e >> 6;
            int m = e & 63;
            int c = c0 + k / KSZ;
            int kk = k % KSZ;
            int mm = mblk + m;
            float v = 0.f;
            if (mm < L_out) v = inb[(size_t)c * in_row_len + mm * cstride + kk];
            As[k][m] = v;
        }
        // load B
#pragma unroll
        for (int e = tid; e < KC * 64; e += 256) {
            int k = e >> 6;
            int n = e & 63;
            Bs[k][n] = wT[(size_t)(c0 * KSZ + k) * 256 + nblk + n];
        }
        __syncthreads();
#pragma unroll
        for (int k = 0; k < KC; k++) {
            float a[4], bb[4];
            *(float4*)a = *(const float4*)&As[k][m0];
            *(float4*)bb = *(const float4*)&Bs[k][n0];
#pragma unroll
            for (int mi = 0; mi < 4; mi++)
#pragma unroll
                for (int ni = 0; ni < 4; ni++) acc[mi][ni] += a[mi] * bb[ni];
        }
        __syncthreads();
    }

    if (!TRANS) {
        // out: [B][256][out_row_len] at column out_off
#pragma unroll
        for (int ni = 0; ni < 4; ni++) {
            float* orow = out + ((size_t)b * DCH + nblk + n0 + ni) * out_row_len + out_off +
                          mblk + m0;
#pragma unroll
            for (int mi = 0; mi < 4; mi++)
                if (mblk + m0 + mi < L_out) orow[mi] = acc[mi][ni];
        }
    } else {
        // out: [B][T = out_row_len][256]
#pragma unroll
        for (int mi = 0; mi < 4; mi++) {
            int mm = mblk + m0 + mi;
            if (mm < L_out) {
                float4 v = make_float4(acc[mi][0], acc[mi][1], acc[mi][2], acc[mi][3]);
                *(float4*)(out + ((size_t)b * out_row_len + mm) * 256 + nblk + n0) = v;
            }
        }
    }
}

// ---------------- final output assembly ----------------
// out[b,o,i,j]; block = (i, b), thread = o (256). Each thread builds the full
// j-row in registers and writes 64 contiguous floats (16x float4).
__global__ void __launch_bounds__(256) final_out(
    const float* __restrict__ P1, const float* __restrict__ P2x,
    const float* __restrict__ P3, const float* __restrict__ Pc,
    const float* __restrict__ vis_b, float* __restrict__ out) {
    int i = blockIdx.x;
    int b = blockIdx.y;
    int o = threadIdx.x;

    __shared__ int lut[64];
    if (o < 64) {
        int j = o;
        int d = j - i;
        int pg = -1;
        if (d >= 1 && d <= 15) {
            pg = c_off[d - 1] + i;
        } else if (d >= 17 && d <= 31 && ((d - 17) & 1) == 0 && (i & 1) == 0) {
            pg = c_off[15 + ((d - 17) >> 1)] + (i >> 1);
        } else if (d >= 35 && d <= 63 && ((d - 35) & 3) == 0 && (i & 3) == 0) {
            pg = c_off[23 + ((d - 35) >> 2)] + (i >> 2);
        }
        lut[j] = pg;
    }
    __syncthreads();

    float vb = __ldg(vis_b + o);
    float p1 = P1[((size_t)b * NG + i) * 256 + o];
    float p2x = P2x[((size_t)b * NG + i) * 256 + o];
    const float* P3b = P3 + (size_t)b * NG * 256 + o;
    const float* Pcb = Pc + (size_t)b * PTOT * 256 + o;

    float accr[64];
#pragma unroll
    for (int j = 0; j < 64; j++) {
        float v = vb;
        if (j == i) {
            v += p1 + p2x + P3b[(size_t)j * 256];
        } else {
            int pg = lut[j];
            if (pg >= 0) v += p1 + Pcb[(size_t)pg * 256] + P3b[(size_t)j * 256];
        }
        accr[j] = v;
    }

    float4* op = (float4*)(out + (((size_t)b * DCH + o) * NG + i) * NG);
#pragma unroll
    for (int q = 0; q < 16; q++)
        op[q] = make_float4(accr[4 * q], accr[4 * q + 1], accr[4 * q + 2], accr[4 * q + 3]);
}

// ---------------- host launcher ----------------
extern "C" void kernel_launch(void* const* d_in, const int* in_sizes, int n_in,
                              void* d_out, int out_size) {
    const float* x   = (const float*)d_in[0];
    const float* w2  = (const float*)d_in[1];
    const float* b2  = (const float*)d_in[2];
    const float* w3  = (const float*)d_in[3];
    const float* b3  = (const float*)d_in[4];
    const float* vw  = (const float*)d_in[5];
    const float* vb  = (const float*)d_in[6];
    float* out = (float*)d_out;

    float *wT2, *wT3, *wTv, *cur, *Pc, *P1, *P2x, *P3;
    cudaGetSymbolAddress((void**)&wT2, g_wT2);
    cudaGetSymbolAddress((void**)&wT3, g_wT3);
    cudaGetSymbolAddress((void**)&wTv, g_wTv);
    cudaGetSymbolAddress((void**)&cur, g_cur);
    cudaGetSymbolAddress((void**)&Pc, g_Pc);
    cudaGetSymbolAddress((void**)&P1, g_P1);
    cudaGetSymbolAddress((void**)&P2x, g_P2x);
    cudaGetSymbolAddress((void**)&P3, g_P3);

    // weight transposes
    transpose_batched<<<dim3(512 / 32, 256 / 32, 29), dim3(32, 8)>>>(w2, wT2, 256, 512);
    transpose_batched<<<dim3(768 / 32, 256 / 32, 2), dim3(32, 8)>>>(w3, wT3, 256, 768);
    transpose_batched<<<dim3(768 / 32, 256 / 32, 1), dim3(32, 8)>>>(vw, wTv, 256, 768);

    // conv chain: 31 sequential layers
    int i2 = 0, i3 = 0;
    int Lprev = NG;
    for (int l = 0; l < 31; l++) {
        int ksz = (l == 15 || l == 23) ? 3 : 2;
        int cs = (ksz == 3) ? 2 : 1;
        int Lout = (Lprev - ksz) / cs + 1;
        const float* inp = (l == 0) ? x : cur;
        int in_row = (l == 0) ? NG : PTOT;
        int in_off = (l == 0) ? 0 : h_off[l - 1];
        dim3 grid(1, 4, BATCH);
        if (ksz == 2) {
            const float* wt = wT2 + (size_t)i2 * 512 * 256;
            const float* bias = b2 + (size_t)i2 * 256;
            i2++;
            conv_gemm<2, false><<<grid, 256>>>(inp, in_row, in_off, cs, wt, bias,
                                               cur, PTOT, h_off[l], Lout);
        } else {
            const float* wt = wT3 + (size_t)i3 * 768 * 256;
            const float* bias = b3 + (size_t)i3 * 256;
            i3++;
            conv_gemm<3, false><<<grid, 256>>>(inp, in_row, in_off, cs, wt, bias,
                                               cur, PTOT, h_off[l], Lout);
        }
        Lprev = Lout;
    }

    // projections of x through the three vis_w slices (K=1 "convs", transposed store)
    conv_gemm<1, true><<<dim3(1, 4, BATCH), 256>>>(x, NG, 0, 1, wTv + 0 * 256 * 256,
                                                   nullptr, P1, NG, 0, NG);
    conv_gemm<1, true><<<dim3(1, 4, BATCH), 256>>>(x, NG, 0, 1, wTv + 1 * 256 * 256,
                                                   nullptr, P2x, NG, 0, NG);
    conv_gemm<1, true><<<dim3(1, 4, BATCH), 256>>>(x, NG, 0, 1, wTv + 2 * 256 * 256,
                                                   nullptr, P3, NG, 0, NG);
    // projection of all conv outputs through W2 slice
    conv_gemm<1, true><<<dim3(17, 4, BATCH), 256>>>(cur, PTOT, 0, 1, wTv + 1 * 256 * 256,
                                                    nullptr, Pc, PTOT, 0, PTOT);

    // assemble output
    final_out<<<dim3(NG, BATCH), 256>>>(P1, P2x, P3, Pc, vb, out);
}

// round 2
// speedup vs baseline: 2.0247x; 2.0247x over previous
#include <cuda_runtime.h>
#include <cstddef>

#define BATCH 32
#define DCH 256
#define NG 64
#define PPAD 1088   // padded total conv positions (17 * 64), all seg offsets %4==0

// padded cumulative segment offsets per layer (31 layers)
__constant__ int c_off[31] = {0,64,128,192,252,312,372,432,488,544,600,656,708,760,812,
                              864,888,912,936,960,980,1000,1020,
                              1040,1048,1056,1064,1072,1076,1080,1084};
static const int h_off[31] = {0,64,128,192,252,312,372,432,488,544,600,656,708,760,812,
                              864,888,912,936,960,980,1000,1020,
                              1040,1048,1056,1064,1072,1076,1080,1084};

// ---------------- scratch ----------------
__device__ float g_wT2[29 * 512 * 256];              // [29][K=512][N=256]
__device__ float g_wT3[2 * 768 * 256];               // [2][K=768][N=256]
__device__ float g_wP[256 * 768];                    // wP[c][s*256+o] = vw[o][s*256+c]
__device__ float g_cur[(size_t)BATCH * DCH * PPAD];  // [B][C][1088]
__device__ float g_Pc[(size_t)BATCH * PPAD * DCH];   // [B][1088][256]
__device__ float g_P[(size_t)BATCH * NG * 768];      // [B][64][768]  (P1|P2x|P3)

// ---------------- f32x2 helpers ----------------
__device__ __forceinline__ void fma2(unsigned long long& d, unsigned long long a,
                                     unsigned long long b) {
    asm("fma.rn.f32x2 %0, %1, %2, %3;" : "=l"(d) : "l"(a), "l"(b), "l"(d));
}
__device__ __forceinline__ unsigned long long dup2(float x) {
    unsigned long long r;
    unsigned int xi = __float_as_uint(x);
    asm("mov.b64 %0, {%1, %1};" : "=l"(r) : "r"(xi));
    return r;
}

// ---------------- generalized transpose ----------------
// out[bat*out_bs + c*out_ld + r] = in[bat*in_bs + r*in_ld + c]
__global__ void trans_k(const float* __restrict__ in, float* __restrict__ out,
                        int R, int C, int in_ld, int out_ld,
                        size_t in_bs, size_t out_bs) {
    __shared__ float tile[32][33];
    int bat = blockIdx.z;
    int c0 = blockIdx.x * 32, r0 = blockIdx.y * 32;
    const float* ib = in + (size_t)bat * in_bs;
    float* ob = out + (size_t)bat * out_bs;
    int tx = threadIdx.x, ty = threadIdx.y;  // 32 x 8
#pragma unroll
    for (int s = 0; s < 32; s += 8) {
        int r = r0 + ty + s, c = c0 + tx;
        if (r < R && c < C) tile[ty + s][tx] = ib[(size_t)r * in_ld + c];
    }
    __syncthreads();
#pragma unroll
    for (int s = 0; s < 32; s += 8) {
        int c = c0 + ty + s, r = r0 + tx;
        if (c < C && r < R) ob[(size_t)c * out_ld + r] = tile[tx][ty + s];
    }
}

// ---------------- conv-as-GEMM (f32x2, double-buffered) ----------------
// out[b, n, m] (!TRANS) or out[b, m, n] (TRANS)
//   = bias[n] + sum_{c,kk} in[b, c, in_off + m*cstride + kk] * wT[(c*KSZ+kk)*wld + n]
// Tile: 64(M) x 64(N), 128 threads, per-thread 4(M) x 8(N).
template <int KSZ, bool TRANS>
__global__ void __launch_bounds__(128) conv_gemm(
    const float* __restrict__ in, int in_row_len, int in_off, int cstride,
    const float* __restrict__ wT, int wld,
    const float* __restrict__ bias,
    float* __restrict__ out, int out_ld, int out_off, int M_total) {
    constexpr int KTOT = KSZ * 256;
    constexpr int KC = (KSZ == 3) ? 24 : 32;
    constexpr int NCH = KTOT / KC;
    constexpr int NA = KC / 2;   // A stage floats per thread
    constexpr int NB = KC / 8;   // B stage float4 per thread

    __shared__ float As[2][KC][64];
    __shared__ float Bs[2][KC][64];

    int b = blockIdx.z;
    int nblk = blockIdx.y * 64;
    int mblk = blockIdx.x * 64;
    int tid = threadIdx.x;
    int m0 = (tid & 15) * 4;
    int n0 = (tid >> 4) * 8;

    const float* inb = in + (size_t)b * DCH * in_row_len + in_off;
    int am = tid & 63;          // A: column (m)
    int ak0 = tid >> 6;         // A: base row
    int bkb = tid >> 4;         // B: base row
    int bn = (tid & 15) * 4;    // B: column group

    float aA[NA];
    float4 bB[NB];

    auto gload = [&](int ch) {
        int c0k = ch * KC;  // starting flat-k of chunk
#pragma unroll
        for (int i = 0; i < NA; i++) {
            int k = c0k + ak0 + 2 * i;
            int c = k / KSZ;
            int kk = k - c * KSZ;
            int mm = mblk + am;
            aA[i] = (mm < M_total)
                        ? inb[(size_t)c * in_row_len + mm * cstride + kk]
                        : 0.f;
        }
#pragma unroll
        for (int i = 0; i < NB; i++) {
            int k = c0k + bkb + 8 * i;
            bB[i] = *(const float4*)&wT[(size_t)k * wld + nblk + bn];
        }
    };
    auto sts = [&](int buf) {
#pragma unroll
        for (int i = 0; i < NA; i++) As[buf][ak0 + 2 * i][am] = aA[i];
#pragma unroll
        for (int i = 0; i < NB; i++)
            *(float4*)&Bs[buf][bkb + 8 * i][bn] = bB[i];
    };

    unsigned long long acc[4][4];
#pragma unroll
    for (int mi = 0; mi < 4; mi++)
#pragma unroll
        for (int p = 0; p < 4; p++) acc[mi][p] = 0ULL;

    gload(0);
    sts(0);
    __syncthreads();

    for (int ch = 0; ch < NCH; ch++) {
        int buf = ch & 1;
        if (ch + 1 < NCH) gload(ch + 1);
#pragma unroll
        for (int k = 0; k < KC; k++) {
            float4 av = *(const float4*)&As[buf][k][m0];
            ulonglong2 bl = *(const ulonglong2*)&Bs[buf][k][n0];
            ulonglong2 bh = *(const ulonglong2*)&Bs[buf][k][n0 + 4];
            unsigned long long a0 = dup2(av.x), a1 = dup2(av.y),
                               a2 = dup2(av.z), a3 = dup2(av.w);
            fma2(acc[0][0], a0, bl.x); fma2(acc[0][1], a0, bl.y);
            fma2(acc[0][2], a0, bh.x); fma2(acc[0][3], a0, bh.y);
            fma2(acc[1][0], a1, bl.x); fma2(acc[1][1], a1, bl.y);
            fma2(acc[1][2], a1, bh.x); fma2(acc[1][3], a1, bh.y);
            fma2(acc[2][0], a2, bl.x); fma2(acc[2][1], a2, bl.y);
            fma2(acc[2][2], a2, bh.x); fma2(acc[2][3], a2, bh.y);
            fma2(acc[3][0], a3, bl.x); fma2(acc[3][1], a3, bl.y);
            fma2(acc[3][2], a3, bh.x); fma2(acc[3][3], a3, bh.y);
        }
        if (ch + 1 < NCH) {
            sts(buf ^ 1);
            __syncthreads();
        }
    }

    // unpack
    float res[4][8];
#pragma unroll
    for (int mi = 0; mi < 4; mi++)
#pragma unroll
        for (int p = 0; p < 4; p++) {
            union { unsigned long long u; float2 f; } cv;
            cv.u = acc[mi][p];
            res[mi][2 * p] = cv.f.x;
            res[mi][2 * p + 1] = cv.f.y;
        }

    if (!TRANS) {
#pragma unroll
        for (int j = 0; j < 8; j++) {
            int n = nblk + n0 + j;
            float bv = bias ? __ldg(bias + n) : 0.f;
            float* orow = out + ((size_t)b * DCH + n) * out_ld + out_off + mblk + m0;
            if (mblk + m0 + 4 <= M_total) {
                float4 v = make_float4(res[0][j] + bv, res[1][j] + bv,
                                       res[2][j] + bv, res[3][j] + bv);
                *(float4*)orow = v;
            } else {
#pragma unroll
                for (int mi = 0; mi < 4; mi++)
                    if (mblk + m0 + mi < M_total) orow[mi] = res[mi][j] + bv;
            }
        }
    } else {
#pragma unroll
        for (int mi = 0; mi < 4; mi++) {
            int mm = mblk + m0 + mi;
            if (mm < M_total) {
                float* op = out + ((size_t)b * M_total + mm) * out_ld + nblk + n0;
                *(float4*)op = make_float4(res[mi][0], res[mi][1], res[mi][2], res[mi][3]);
                *(float4*)(op + 4) =
                    make_float4(res[mi][4], res[mi][5], res[mi][6], res[mi][7]);
            }
        }
    }
}

// ---------------- final output assembly ----------------
__global__ void __launch_bounds__(256) final_out(
    const float* __restrict__ P, const float* __restrict__ Pc,
    const float* __restrict__ vis_b, float* __restrict__ out) {
    int i = blockIdx.x;
    int b = blockIdx.y;
    int o = threadIdx.x;

    __shared__ int lut[64];
    if (o < 64) {
        int j = o;
        int d = j - i;
        int pg = -1;
        if (d >= 1 && d <= 15) {
            pg = c_off[d - 1] + i;
        } else if (d >= 17 && d <= 31 && ((d - 17) & 1) == 0 && (i & 1) == 0) {
            pg = c_off[15 + ((d - 17) >> 1)] + (i >> 1);
        } else if (d >= 35 && d <= 63 && ((d - 35) & 3) == 0 && (i & 3) == 0) {
            pg = c_off[23 + ((d - 35) >> 2)] + (i >> 2);
        }
        lut[j] = pg;
    }
    __syncthreads();

    float vb = __ldg(vis_b + o);
    float p1 = P[((size_t)b * NG + i) * 768 + o];
    float p2x = P[((size_t)b * NG + i) * 768 + 256 + o];
    const float* P3b = P + (size_t)b * NG * 768 + 512 + o;
    const float* Pcb = Pc + (size_t)b * PPAD * 256 + o;

    float accr[64];
#pragma unroll
    for (int j = 0; j < 64; j++) {
        float v = vb;
        if (j == i) {
            v += p1 + p2x + P3b[(size_t)j * 768];
        } else {
            int pg = lut[j];
            if (pg >= 0) v += p1 + Pcb[(size_t)pg * 256] + P3b[(size_t)j * 768];
        }
        accr[j] = v;
    }

    float4* op = (float4*)(out + (((size_t)b * DCH + o) * NG + i) * NG);
#pragma unroll
    for (int q = 0; q < 16; q++)
        op[q] = make_float4(accr[4 * q], accr[4 * q + 1], accr[4 * q + 2], accr[4 * q + 3]);
}

// ---------------- host launcher ----------------
extern "C" void kernel_launch(void* const* d_in, const int* in_sizes, int n_in,
                              void* d_out, int out_size) {
    const float* x  = (const float*)d_in[0];
    const float* w2 = (const float*)d_in[1];
    const float* b2 = (const float*)d_in[2];
    const float* w3 = (const float*)d_in[3];
    const float* b3 = (const float*)d_in[4];
    const float* vw = (const float*)d_in[5];
    const float* vb = (const float*)d_in[6];
    float* out = (float*)d_out;

    float *wT2, *wT3, *wP, *cur, *Pc, *P;
    cudaGetSymbolAddress((void**)&wT2, g_wT2);
    cudaGetSymbolAddress((void**)&wT3, g_wT3);
    cudaGetSymbolAddress((void**)&wP, g_wP);
    cudaGetSymbolAddress((void**)&cur, g_cur);
    cudaGetSymbolAddress((void**)&Pc, g_Pc);
    cudaGetSymbolAddress((void**)&P, g_P);

    dim3 tb(32, 8);
    // w2: [29][256][512] -> [29][512][256]
    trans_k<<<dim3(512 / 32, 256 / 32, 29), tb>>>(w2, wT2, 256, 512, 512, 256,
                                                  (size_t)256 * 512, (size_t)256 * 512);
    // w3: [2][256][768] -> [2][768][256]
    trans_k<<<dim3(768 / 32, 256 / 32, 2), tb>>>(w3, wT3, 256, 768, 768, 256,
                                                 (size_t)256 * 768, (size_t)256 * 768);
    // vw [256][768] -> wP[c][s*256+o], 3 slice-batches
    trans_k<<<dim3(256 / 32, 256 / 32, 3), tb>>>(vw, wP, 256, 256, 768, 768,
                                                 (size_t)256, (size_t)256);

    // conv chain: 31 sequential layers
    int i2 = 0, i3 = 0;
    int Lprev = NG;
    for (int l = 0; l < 31; l++) {
        int ksz = (l == 15 || l == 23) ? 3 : 2;
        int cs = (ksz == 3) ? 2 : 1;
        int Lout = (Lprev - ksz) / cs + 1;
        const float* inp = (l == 0) ? x : cur;
        int in_row = (l == 0) ? NG : PPAD;
        int in_off = (l == 0) ? 0 : h_off[l - 1];
        dim3 grid(1, 4, BATCH);
        if (ksz == 2) {
            conv_gemm<2, false><<<grid, 128>>>(inp, in_row, in_off, cs,
                                               wT2 + (size_t)i2 * 512 * 256, 256,
                                               b2 + (size_t)i2 * 256,
                                               cur, PPAD, h_off[l], Lout);
            i2++;
        } else {
            conv_gemm<3, false><<<grid, 128>>>(inp, in_row, in_off, cs,
                                               wT3 + (size_t)i3 * 768 * 256, 256,
                                               b3 + (size_t)i3 * 256,
                                               cur, PPAD, h_off[l], Lout);
            i3++;
        }
        Lprev = Lout;
    }

    // merged projections of x through all three vis_w slices: [B][64][768]
    conv_gemm<1, true><<<dim3(1, 12, BATCH), 128>>>(x, NG, 0, 1, wP, 768, nullptr,
                                                    P, 768, 0, NG);
    // projection of all conv outputs through middle slice: [B][1088][256]
    conv_gemm<1, true><<<dim3(17, 4, BATCH), 128>>>(cur, PPAD, 0, 1, wP + 256, 768,
                                                    nullptr, Pc, 256, 0, PPAD);

    final_out<<<dim3(NG, BATCH), 256>>>(P, Pc, vb, out);
}

// round 3
// speedup vs baseline: 2.9505x; 1.4572x over previous
#include <cuda_runtime.h>
#include <cstddef>

#define BATCH 32
#define DCH 256
#define NG 64
#define PPAD 1088   // padded total conv positions (17 * 64)

__constant__ int c_off[31] = {0,64,128,192,252,312,372,432,488,544,600,656,708,760,812,
                              864,888,912,936,960,980,1000,1020,
                              1040,1048,1056,1064,1072,1076,1080,1084};
static const int h_off[31] = {0,64,128,192,252,312,372,432,488,544,600,656,708,760,812,
                              864,888,912,936,960,980,1000,1020,
                              1040,1048,1056,1064,1072,1076,1080,1084};

// ---------------- scratch ----------------
__device__ float g_wT2[29 * 512 * 256];
__device__ float g_wT3[2 * 768 * 256];
__device__ float g_wP[256 * 768];
__device__ float g_cur[(size_t)BATCH * DCH * PPAD];
__device__ float g_Pc[(size_t)BATCH * PPAD * DCH];
__device__ float g_P[(size_t)BATCH * NG * 768];

// ---------------- f32x2 helpers ----------------
__device__ __forceinline__ void fma2(unsigned long long& d, unsigned long long a,
                                     unsigned long long b) {
    asm("fma.rn.f32x2 %0, %1, %2, %3;" : "=l"(d) : "l"(a), "l"(b), "l"(d));
}
__device__ __forceinline__ unsigned long long dup2(float x) {
    unsigned long long r;
    unsigned int xi = __float_as_uint(x);
    asm("mov.b64 %0, {%1, %1};" : "=l"(r) : "r"(xi));
    return r;
}

// ---------------- generalized transpose ----------------
__global__ void trans_k(const float* __restrict__ in, float* __restrict__ out,
                        int R, int C, int in_ld, int out_ld,
                        size_t in_bs, size_t out_bs) {
    __shared__ float tile[32][33];
    int bat = blockIdx.z;
    int c0 = blockIdx.x * 32, r0 = blockIdx.y * 32;
    const float* ib = in + (size_t)bat * in_bs;
    float* ob = out + (size_t)bat * out_bs;
    int tx = threadIdx.x, ty = threadIdx.y;
#pragma unroll
    for (int s = 0; s < 32; s += 8) {
        int r = r0 + ty + s, c = c0 + tx;
        if (r < R && c < C) tile[ty + s][tx] = ib[(size_t)r * in_ld + c];
    }
    __syncthreads();
#pragma unroll
    for (int s = 0; s < 32; s += 8) {
        int c = c0 + ty + s, r = r0 + tx;
        if (c < C && r < R) ob[(size_t)c * out_ld + r] = tile[tx][ty + s];
    }
}

// ---------------- conv-as-GEMM: 256 threads, 2 warpgroups split K ----------------
// out[b, n, m] (!TRANS) or out[b, m, n] (TRANS)
//   = bias[n] + sum_{c,kk} in[b, c, in_off + m*cstride + kk] * wT[(c*KSZ+kk)*wld + n]
template <int KSZ, int TM, bool TRANS>
__global__ void __launch_bounds__(256) conv_gemm(
    const float* __restrict__ in, int in_row_len, int in_off, int cstride,
    const float* __restrict__ wT, int wld,
    const float* __restrict__ bias,
    float* __restrict__ out, int out_ld, int out_off, int M_total) {
    constexpr int KTOT = KSZ * 256;
    constexpr int KH = KTOT / 2;                 // per-warpgroup K
    constexpr int KC = (KSZ == 3) ? 24 : 32;     // K chunk
    constexpr int NCH = KH / KC;
    constexpr int AG = 128 / TM;                 // A-load row groups
    constexpr int NA = KC / AG;
    constexpr int NB = KC / 8;
    constexpr int MR = TM / 16;                  // per-thread M rows
    constexpr int WGS = 2 * KC * TM + 2 * KC * 64;  // floats per warpgroup block

    extern __shared__ float smem[];
    int tid = threadIdx.x;
    int wg = tid >> 7;
    int wtid = tid & 127;
    float* As = smem + wg * WGS;
    float* Bs = As + 2 * KC * TM;
    float* Red = smem + 2 * WGS;                 // [TM][64]

    int b = blockIdx.z;
    int nblk = blockIdx.y * 64;
    int mblk = blockIdx.x * TM;
    int m0 = (wtid & 15) * MR;
    int n0 = (wtid >> 4) * 8;

    int am = wtid % TM;
    int ak0 = wtid / TM;
    int bkb = wtid >> 4;
    int bn = (wtid & 15) * 4;

    const float* inb = in + (size_t)b * DCH * in_row_len + in_off;
    int kbase = wg * KH;

    float aA[NA];
    float4 bB[NB];
    auto gload = [&](int ch) {
        int c0k = kbase + ch * KC;
#pragma unroll
        for (int i = 0; i < NA; i++) {
            int k = c0k + ak0 + AG * i;
            int c = k / KSZ;
            int kk = k - c * KSZ;
            int mm = mblk + am;
            aA[i] = (mm < M_total)
                        ? inb[(size_t)c * in_row_len + mm * cstride + kk]
                        : 0.f;
        }
#pragma unroll
        for (int i = 0; i < NB; i++) {
            int k = c0k + bkb + 8 * i;
            bB[i] = *(const float4*)&wT[(size_t)k * wld + nblk + bn];
        }
    };
    auto sts = [&](int buf) {
#pragma unroll
        for (int i = 0; i < NA; i++)
            As[buf * KC * TM + (ak0 + AG * i) * TM + am] = aA[i];
#pragma unroll
        for (int i = 0; i < NB; i++)
            *(float4*)&Bs[buf * KC * 64 + (bkb + 8 * i) * 64 + bn] = bB[i];
    };

    unsigned long long acc[MR][4];
#pragma unroll
    for (int mi = 0; mi < MR; mi++)
#pragma unroll
        for (int p = 0; p < 4; p++) acc[mi][p] = 0ULL;

    gload(0);
    sts(0);
    __syncthreads();

    for (int ch = 0; ch < NCH; ch++) {
        int buf = ch & 1;
        if (ch + 1 < NCH) gload(ch + 1);
#pragma unroll
        for (int k = 0; k < KC; k++) {
            float a[MR];
            const float* ap = &As[buf * KC * TM + k * TM + m0];
            if (MR == 4) {
                float4 v = *(const float4*)ap;
                a[0] = v.x; a[1] = v.y; a[2] = v.z; a[3] = v.w;
            } else if (MR == 2) {
                float2 v = *(const float2*)ap;
                a[0] = v.x; a[1] = v.y;
            } else {
                a[0] = *ap;
            }
            const float* bp = &Bs[buf * KC * 64 + k * 64 + n0];
            ulonglong2 bl = *(const ulonglong2*)bp;
            ulonglong2 bh = *(const ulonglong2*)(bp + 4);
#pragma unroll
            for (int mi = 0; mi < MR; mi++) {
                unsigned long long ad = dup2(a[mi]);
                fma2(acc[mi][0], ad, bl.x);
                fma2(acc[mi][1], ad, bl.y);
                fma2(acc[mi][2], ad, bh.x);
                fma2(acc[mi][3], ad, bh.y);
            }
        }
        if (ch + 1 < NCH) {
            sts(buf ^ 1);
            __syncthreads();
        }
    }

    float res[MR][8];
#pragma unroll
    for (int mi = 0; mi < MR; mi++)
#pragma unroll
        for (int p = 0; p < 4; p++) {
            union { unsigned long long u; float2 f; } cv;
            cv.u = acc[mi][p];
            res[mi][2 * p] = cv.f.x;
            res[mi][2 * p + 1] = cv.f.y;
        }

    __syncthreads();
    if (wg == 1) {
#pragma unroll
        for (int mi = 0; mi < MR; mi++) {
            float* rp = &Red[(m0 + mi) * 64 + n0];
            *(float4*)rp = make_float4(res[mi][0], res[mi][1], res[mi][2], res[mi][3]);
            *(float4*)(rp + 4) =
                make_float4(res[mi][4], res[mi][5], res[mi][6], res[mi][7]);
        }
    }
    __syncthreads();
    if (wg != 0) return;

#pragma unroll
    for (int mi = 0; mi < MR; mi++) {
        const float* rp = &Red[(m0 + mi) * 64 + n0];
#pragma unroll
        for (int j = 0; j < 8; j++) res[mi][j] += rp[j];
    }

    if (!TRANS) {
#pragma unroll
        for (int j = 0; j < 8; j++) {
            int n = nblk + n0 + j;
            float bv = bias ? __ldg(bias + n) : 0.f;
            float* orow = out + ((size_t)b * DCH + n) * out_ld + out_off + mblk + m0;
            if (mblk + m0 + MR <= M_total) {
                if (MR == 4) {
                    *(float4*)orow = make_float4(res[0][j] + bv, res[1][j] + bv,
                                                 res[2][j] + bv, res[3][j] + bv);
                } else if (MR == 2) {
                    *(float2*)orow = make_float2(res[0][j] + bv, res[1][j] + bv);
                } else {
                    orow[0] = res[0][j] + bv;
                }
            } else {
#pragma unroll
                for (int mi = 0; mi < MR; mi++)
                    if (mblk + m0 + mi < M_total) orow[mi] = res[mi][j] + bv;
            }
        }
    } else {
#pragma unroll
        for (int mi = 0; mi < MR; mi++) {
            int mm = mblk + m0 + mi;
            if (mm < M_total) {
                float* op = out + ((size_t)b * M_total + mm) * out_ld + nblk + n0;
                *(float4*)op = make_float4(res[mi][0], res[mi][1], res[mi][2], res[mi][3]);
                *(float4*)(op + 4) =
                    make_float4(res[mi][4], res[mi][5], res[mi][6], res[mi][7]);
            }
        }
    }
}

// ---------------- final output assembly ----------------
__global__ void __launch_bounds__(256) final_out(
    const float* __restrict__ P, const float* __restrict__ Pc,
    const float* __restrict__ vis_b, float* __restrict__ out) {
    int i = blockIdx.x;
    int b = blockIdx.y;
    int o = threadIdx.x;

    __shared__ int lut[64];
    if (o < 64) {
        int j = o;
        int d = j - i;
        int pg = -1;
        if (d >= 1 && d <= 15) {
            pg = c_off[d - 1] + i;
        } else if (d >= 17 && d <= 31 && ((d - 17) & 1) == 0 && (i & 1) == 0) {
            pg = c_off[15 + ((d - 17) >> 1)] + (i >> 1);
        } else if (d >= 35 && d <= 63 && ((d - 35) & 3) == 0 && (i & 3) == 0) {
            pg = c_off[23 + ((d - 35) >> 2)] + (i >> 2);
        }
        lut[j] = pg;
    }
    __syncthreads();

    float vb = __ldg(vis_b + o);
    float p1 = P[((size_t)b * NG + i) * 768 + o];
    float p2x = P[((size_t)b * NG + i) * 768 + 256 + o];
    const float* P3b = P + (size_t)b * NG * 768 + 512 + o;
    const float* Pcb = Pc + (size_t)b * PPAD * 256 + o;

    float accr[64];
#pragma unroll
    for (int j = 0; j < 64; j++) {
        float v = vb;
        if (j == i) {
            v += p1 + p2x + P3b[(size_t)j * 768];
        } else {
            int pg = lut[j];
            if (pg >= 0) v += p1 + Pcb[(size_t)pg * 256] + P3b[(size_t)j * 768];
        }
        accr[j] = v;
    }

    float4* op = (float4*)(out + (((size_t)b * DCH + o) * NG + i) * NG);
#pragma unroll
    for (int q = 0; q < 16; q++)
        op[q] = make_float4(accr[4 * q], accr[4 * q + 1], accr[4 * q + 2], accr[4 * q + 3]);
}

// ---------------- host ----------------
static inline int smem_bytes(int ksz, int tm) {
    int kc = (ksz == 3) ? 24 : 32;
    return (2 * (2 * kc * tm + 2 * kc * 64) + tm * 64) * 4;
}

extern "C" void kernel_launch(void* const* d_in, const int* in_sizes, int n_in,
                              void* d_out, int out_size) {
    const float* x  = (const float*)d_in[0];
    const float* w2 = (const float*)d_in[1];
    const float* b2 = (const float*)d_in[2];
    const float* w3 = (const float*)d_in[3];
    const float* b3 = (const float*)d_in[4];
    const float* vw = (const float*)d_in[5];
    const float* vb = (const float*)d_in[6];
    float* out = (float*)d_out;

    float *wT2, *wT3, *wP, *cur, *Pc, *P;
    cudaGetSymbolAddress((void**)&wT2, g_wT2);
    cudaGetSymbolAddress((void**)&wT3, g_wT3);
    cudaGetSymbolAddress((void**)&wP, g_wP);
    cudaGetSymbolAddress((void**)&cur, g_cur);
    cudaGetSymbolAddress((void**)&Pc, g_Pc);
    cudaGetSymbolAddress((void**)&P, g_P);

    // opt-in SMEM for all instantiations (host-side attr; capture-safe)
    cudaFuncSetAttribute(conv_gemm<2, 64, false>,
                         cudaFuncAttributeMaxDynamicSharedMemorySize, smem_bytes(2, 64));
    cudaFuncSetAttribute(conv_gemm<2, 32, false>,
                         cudaFuncAttributeMaxDynamicSharedMemorySize, smem_bytes(2, 32));
    cudaFuncSetAttribute(conv_gemm<2, 16, false>,
                         cudaFuncAttributeMaxDynamicSharedMemorySize, smem_bytes(2, 16));
    cudaFuncSetAttribute(conv_gemm<3, 32, false>,
                         cudaFuncAttributeMaxDynamicSharedMemorySize, smem_bytes(3, 32));
    cudaFuncSetAttribute(conv_gemm<3, 16, false>,
                         cudaFuncAttributeMaxDynamicSharedMemorySize, smem_bytes(3, 16));
    cudaFuncSetAttribute(conv_gemm<1, 64, true>,
                         cudaFuncAttributeMaxDynamicSharedMemorySize, smem_bytes(1, 64));

    dim3 tb(32, 8);
    trans_k<<<dim3(512 / 32, 256 / 32, 29), tb>>>(w2, wT2, 256, 512, 512, 256,
                                                  (size_t)256 * 512, (size_t)256 * 512);
    trans_k<<<dim3(768 / 32, 256 / 32, 2), tb>>>(w3, wT3, 256, 768, 768, 256,
                                                 (size_t)256 * 768, (size_t)256 * 768);
    trans_k<<<dim3(256 / 32, 256 / 32, 3), tb>>>(vw, wP, 256, 256, 768, 768,
                                                 (size_t)256, (size_t)256);

    int i2 = 0, i3 = 0;
    int Lprev = NG;
    for (int l = 0; l < 31; l++) {
        int ksz = (l == 15 || l == 23) ? 3 : 2;
        int cs = (ksz == 3) ? 2 : 1;
        int Lout = (Lprev - ksz) / cs + 1;
        const float* inp = (l == 0) ? x : cur;
        int in_row = (l == 0) ? NG : PPAD;
        int in_off = (l == 0) ? 0 : h_off[l - 1];
        dim3 grid(1, 4, BATCH);
        if (ksz == 2) {
            const float* wt = wT2 + (size_t)i2 * 512 * 256;
            const float* bi = b2 + (size_t)i2 * 256;
            i2++;
            if (Lout > 32)
                conv_gemm<2, 64, false><<<grid, 256, smem_bytes(2, 64)>>>(
                    inp, in_row, in_off, cs, wt, 256, bi, cur, PPAD, h_off[l], Lout);
            else if (Lout > 16)
                conv_gemm<2, 32, false><<<grid, 256, smem_bytes(2, 32)>>>(
                    inp, in_row, in_off, cs, wt, 256, bi, cur, PPAD, h_off[l], Lout);
            else
                conv_gemm<2, 16, false><<<grid, 256, smem_bytes(2, 16)>>>(
                    inp, in_row, in_off, cs, wt, 256, bi, cur, PPAD, h_off[l], Lout);
        } else {
            const float* wt = wT3 + (size_t)i3 * 768 * 256;
            const float* bi = b3 + (size_t)i3 * 256;
            i3++;
            if (Lout > 16)
                conv_gemm<3, 32, false><<<grid, 256, smem_bytes(3, 32)>>>(
                    inp, in_row, in_off, cs, wt, 256, bi, cur, PPAD, h_off[l], Lout);
            else
                conv_gemm<3, 16, false><<<grid, 256, smem_bytes(3, 16)>>>(
                    inp, in_row, in_off, cs, wt, 256, bi, cur, PPAD, h_off[l], Lout);
        }
        Lprev = Lout;
    }

    // merged x projections: [B][64][768]
    conv_gemm<1, 64, true><<<dim3(1, 12, BATCH), 256, smem_bytes(1, 64)>>>(
        x, NG, 0, 1, wP, 768, nullptr, P, 768, 0, NG);
    // Pc: [B][1088][256]
    conv_gemm<1, 64, true><<<dim3(17, 4, BATCH), 256, smem_bytes(1, 64)>>>(
        cur, PPAD, 0, 1, wP + 256, 768, nullptr, Pc, 256, 0, PPAD);

    final_out<<<dim3(NG, BATCH), 256>>>(P, Pc, vb, out);
}